// round 15
// baseline (speedup 1.0000x reference)
#include <cuda_runtime.h>
#include <cstdint>

// RankingLoss: B=16384 rows, C=1000 classes.
// Persistent single-wave (152 CTAs), warp-specialized: 8 consumer warps + 1
// producer warp per CTA. Chunk = 8 contiguous rows; TMA moves 32000 B (128B-
// aligned) per array per chunk through a 3-stage ring. Consumer warp w reduces
// row w of each chunk (REDUX argmax + margin sum), fully warp-autonomous.

#define C_CLASSES  1000
#define C4         250
#define ROW_BYTES  4000
#define ROWS_PC    8                       // rows per chunk
#define CHUNK_B    (ROWS_PC * ROW_BYTES)   // 32000 (= 250*128, 128B aligned)
#define STAGE_B    (2 * CHUNK_B)           // tgt + lgt = 64000
#define STAGES     3
#define CWARPS     8
#define THREADS    ((CWARPS + 1) * 32)     // 288
#define GRID       152
#define VS         8                       // vec4 slots per lane

__device__ float    g_scratch;   // zero-init at module load; reset by last block
__device__ unsigned g_count;

__device__ __forceinline__ unsigned su32(const void* p) {
    return (unsigned)__cvta_generic_to_shared(p);
}

__device__ __forceinline__ void bulk_ldg(unsigned dst, const void* src,
                                         unsigned bytes, unsigned mbar) {
    asm volatile(
        "cp.async.bulk.shared::cta.global.mbarrier::complete_tx::bytes [%0], [%1], %2, [%3];"
        :: "r"(dst), "l"(src), "r"(bytes), "r"(mbar) : "memory");
}

__device__ __forceinline__ void mbar_wait(unsigned mbar, unsigned phase) {
    unsigned done;
    asm volatile(
        "{\n\t.reg .pred p;\n\t"
        "mbarrier.try_wait.parity.acquire.cta.shared::cta.b64 p, [%1], %2, 0x989680;\n\t"
        "selp.b32 %0, 1, 0, p;\n\t}"
        : "=r"(done) : "r"(mbar), "r"(phase) : "memory");
    while (!done) {
        asm volatile(
            "{\n\t.reg .pred p;\n\t"
            "mbarrier.try_wait.parity.acquire.cta.shared::cta.b64 p, [%1], %2, 0x989680;\n\t"
            "selp.b32 %0, 1, 0, p;\n\t}"
            : "=r"(done) : "r"(mbar), "r"(phase) : "memory");
    }
}

extern __shared__ char dynbuf[];   // [STAGES][STAGE_B]

__global__ __launch_bounds__(THREADS)
void ranking_loss_kernel(const float* __restrict__ logits,
                         const float* __restrict__ target,
                         float* __restrict__ out,
                         float inv_B, int nchunks) {
    __shared__ alignas(8) unsigned long long full_mb[STAGES];
    __shared__ alignas(8) unsigned long long empty_mb[STAGES];
    __shared__ float s_sum[CWARPS];

    const int t    = threadIdx.x;
    const int lane = t & 31;
    const int warp = t >> 5;                 // 0..7 consumers, 8 producer
    const unsigned fullm = 0xffffffffu;
    const int bid  = blockIdx.x;

    if (t == 0) {
        #pragma unroll
        for (int s = 0; s < STAGES; s++) {
            asm volatile("mbarrier.init.shared.b64 [%0], 1;"
                         :: "r"(su32(&full_mb[s])) : "memory");
            asm volatile("mbarrier.init.shared.b64 [%0], %1;"
                         :: "r"(su32(&empty_mb[s])), "r"(CWARPS) : "memory");
        }
        asm volatile("fence.proxy.async.shared::cta;" ::: "memory");
    }
    __syncthreads();

    float loss = 0.f;

    if (warp == CWARPS) {
        // ---------------- producer warp (lane 0 only) ----------------
        if (lane == 0) {
            int i = 0;
            for (int c = bid; c < nchunks; c += GRID, i++) {
                const int s = i % STAGES;
                // empty-wait with flipped initial phase: first STAGES pass free
                mbar_wait(su32(&empty_mb[s]), 1u ^ ((unsigned)(i / STAGES) & 1u));
                const unsigned fb = su32(&full_mb[s]);
                asm volatile("mbarrier.arrive.expect_tx.shared.b64 _, [%0], %1;"
                             :: "r"(fb), "r"(STAGE_B) : "memory");
                const size_t elem0 = (size_t)c * (ROWS_PC * C_CLASSES);
                const unsigned sb = su32(dynbuf + s * STAGE_B);
                bulk_ldg(sb,           target + elem0, CHUNK_B, fb);
                bulk_ldg(sb + CHUNK_B, logits + elem0, CHUNK_B, fb);
            }
        }
    } else {
        // ---------------- consumer warps: warp w owns row w of each chunk ----
        int i = 0;
        for (int c = bid; c < nchunks; c += GRID, i++) {
            const int s = i % STAGES;
            mbar_wait(su32(&full_mb[s]), (unsigned)(i / STAGES) & 1u);

            const char* sbase = dynbuf + s * STAGE_B;
            const float4* tg4 = reinterpret_cast<const float4*>(sbase + warp * ROW_BYTES);
            const float4* lg4 = reinterpret_cast<const float4*>(sbase + CHUNK_B + warp * ROW_BYTES);

            // ---- pass 1: warp argmax over targets, carrying the paired logit ----
            float m   = -1.f;                 // below any uniform[0,1) target
            int   mi  = 0x7fffffff;
            float mlx = 0.f;
            #pragma unroll
            for (int v0 = 0; v0 < VS; v0++) {
                const int v = v0 * 32 + lane;
                if (v < C4) {
                    const float4 tvv = tg4[v];
                    const float4 lvv = lg4[v];
                    const int base = 4 * v;
                    const float ta[4] = {tvv.x, tvv.y, tvv.z, tvv.w};
                    const float la[4] = {lvv.x, lvv.y, lvv.z, lvv.w};
                    #pragma unroll
                    for (int k = 0; k < 4; k++)   // ascending index: strict > keeps first
                        if (ta[k] > m) { m = ta[k]; mi = base + k; mlx = la[k]; }
                }
            }

            // targets >= 0: positive-float bits order-preserving as u32
            const unsigned mb   = __float_as_uint(m);
            const unsigned wmb  = __reduce_max_sync(fullm, mb);
            const unsigned cand = (mb == wmb) ? (unsigned)mi : 0xffffffffu;
            const unsigned wmi  = __reduce_min_sync(fullm, cand);
            const unsigned own  = __ballot_sync(fullm, (mb == wmb) & ((unsigned)mi == wmi));
            const float x1      = __shfl_sync(fullm, mlx, __ffs(own) - 1);
            const int label     = (int)wmi;

            // ---- pass 2: margin-relu sum (re-read logits from smem) ----
            if (label != 0) {
                const float inv_pos = 1.0f / (float)(C_CLASSES - 1);
                const float flabel  = (float)label;
                const float nx1     = -x1;
                #pragma unroll
                for (int v0 = 0; v0 < VS; v0++) {
                    const int v = v0 * 32 + lane;
                    if (v < C4) {
                        const float4 lvv = lg4[v];
                        const float la[4] = {lvv.x, lvv.y, lvv.z, lvv.w};
                        const float fb = (float)(4 * v);
                        #pragma unroll
                        for (int k = 0; k < 4; k++) {
                            // j==0 only at v==0,k==0 (lane 0): margin = 1.0
                            const float margin = (v == 0 && k == 0)
                                               ? 1.0f
                                               : fabsf(flabel - (fb + (float)k)) * inv_pos;
                            loss += fmaxf(0.f, la[k] + nx1 + margin);
                        }
                    }
                }
            }

            // ---- release this stage: warp done reading ----
            __syncwarp();
            if (lane == 0) {
                asm volatile("fence.proxy.async.shared::cta;" ::: "memory");
                asm volatile("mbarrier.arrive.shared.b64 _, [%0];"
                             :: "r"(su32(&empty_mb[s])) : "memory");
            }
        }

        // ---- warp sum ----
        #pragma unroll
        for (int off = 16; off > 0; off >>= 1)
            loss += __shfl_down_sync(fullm, loss, off);
        if (lane == 0) s_sum[warp] = loss;
    }

    __syncthreads();

    if (t == 0) {
        float total = 0.f;
        #pragma unroll
        for (int w = 0; w < CWARPS; w++) total += s_sum[w];
        atomicAdd(&g_scratch, total);
        __threadfence();
        const unsigned done = atomicAdd(&g_count, 1u);
        if (done == gridDim.x - 1) {                 // last block finalizes
            __threadfence();
            const float acc = *((volatile float*)&g_scratch);
            out[0] = acc * inv_B;
            g_scratch = 0.f;                         // reset for next graph replay
            g_count   = 0u;
            __threadfence();
        }
    }
}

extern "C" void kernel_launch(void* const* d_in, const int* in_sizes, int n_in,
                              void* d_out, int out_size) {
    const float* logits = (const float*)d_in[0];
    const float* target = (const float*)d_in[1];
    float* out = (float*)d_out;

    const int B = in_sizes[0] / C_CLASSES;           // 16384
    const int nchunks = B / ROWS_PC;                 // 2048
    const int smem = STAGES * STAGE_B;               // 192000

    cudaFuncSetAttribute(ranking_loss_kernel,
                         cudaFuncAttributeMaxDynamicSharedMemorySize, smem);
    ranking_loss_kernel<<<GRID, THREADS, smem>>>(logits, target, out,
                                                 1.0f / (float)B, nchunks);
}